// round 4
// baseline (speedup 1.0000x reference)
#include <cuda_runtime.h>
#include <cuda_bf16.h>
#include <cstdint>

// Problem constants (fixed by the dataset)
#define NN 50000
#define NE 1600000
#define NT 50
#define FDT 0.02f

// Persistent-kernel geometry: 296 = 148 SMs * 2 blocks, guaranteed co-resident
#define PBLK 296
#define THREADS 512
#define GPB (THREADS / 8)           // 64 groups of 8 lanes per block
#define NGROUPS (PBLK * GPB)        // 18944
#define MAXK 3                      // ceil(NN / NGROUPS)

// ---------------- device scratch (static, no allocations) ----------------
__device__ float2 g_csc[NE];            // per edge: {weight, bitcast(tgt)} sorted by SOURCE
__device__ int    g_row_start[NN + 1];  // CSC row offsets (by source)
__device__ int    g_deg[NN];
__device__ int    g_cursor[NN];
__device__ float  g_acc[2][NN * 4];     // double-buffered synaptic accumulator [node][batch]
__device__ float  g_alpha[NN];          // dt / max(tau, dt)
__device__ int    g_bar;                // global barrier arrival counter

__device__ __forceinline__ void red_v4(float* p, float a, float b, float c, float d) {
    asm volatile("red.global.add.v4.f32 [%0], {%1, %2, %3, %4};"
                 :: "l"(p), "f"(a), "f"(b), "f"(c), "f"(d) : "memory");
}

// ---------------- prep kernels ----------------
__global__ void init_kernel(const float* __restrict__ tc) {
    int i = blockIdx.x * blockDim.x + threadIdx.x;
    if (i == 0) g_bar = 0;
    if (i < NN) {
        g_deg[i] = 0;
        g_cursor[i] = 0;
        g_alpha[i] = FDT / fmaxf(tc[i], FDT);
        float4 z = make_float4(0.f, 0.f, 0.f, 0.f);
        *reinterpret_cast<float4*>(&g_acc[0][4 * i]) = z;
        *reinterpret_cast<float4*>(&g_acc[1][4 * i]) = z;
    }
}

__global__ void hist_kernel(const int* __restrict__ src) {
    int i = blockIdx.x * blockDim.x + threadIdx.x;
    if (i < NE) atomicAdd(&g_deg[src[i]], 1);
}

// Single-block exclusive scan over g_deg -> g_row_start
__global__ void scan_kernel() {
    __shared__ int warp_sums[32];
    __shared__ int s_carry;
    const int tid = threadIdx.x;
    const int lane = tid & 31, wid = tid >> 5;
    if (tid == 0) s_carry = 0;
    __syncthreads();
    for (int base = 0; base < NN; base += 1024) {
        int i = base + tid;
        int v = (i < NN) ? g_deg[i] : 0;
        int x = v;
        #pragma unroll
        for (int o = 1; o < 32; o <<= 1) {
            int y = __shfl_up_sync(0xffffffffu, x, o);
            if (lane >= o) x += y;
        }
        if (lane == 31) warp_sums[wid] = x;
        __syncthreads();
        if (wid == 0) {
            int w = warp_sums[lane];
            #pragma unroll
            for (int o = 1; o < 32; o <<= 1) {
                int y = __shfl_up_sync(0xffffffffu, w, o);
                if (lane >= o) w += y;
            }
            warp_sums[lane] = w;
        }
        __syncthreads();
        int warp_off = (wid == 0) ? 0 : warp_sums[wid - 1];
        int incl = x + warp_off;
        int carry = s_carry;
        if (i < NN) g_row_start[i] = carry + incl - v;
        __syncthreads();
        if (tid == 1023) s_carry = carry + incl;
        __syncthreads();
    }
    if (tid == 0) g_row_start[NN] = s_carry;
}

__global__ void scatter_kernel(const int* __restrict__ src, const int* __restrict__ tgt,
                               const float* __restrict__ sign, const float* __restrict__ cnt,
                               const float* __restrict__ strg) {
    int i = blockIdx.x * blockDim.x + threadIdx.x;
    if (i >= NE) return;
    float w = sign[i] * fmaxf(cnt[i], 0.0f) * fmaxf(strg[i], 0.0f);
    int s = src[i];
    int pos = atomicAdd(&g_cursor[s], 1);
    g_csc[g_row_start[s] + pos] = make_float2(w, __int_as_float(tgt[i]));
}

// ---------------- persistent kernel: all 50 steps, scatter-RED formulation ----------------
__global__ void __launch_bounds__(THREADS, 2) net_kernel(const float* __restrict__ bias,
                                                         const float* __restrict__ x,
                                                         float* __restrict__ out) {
    const int tid = threadIdx.x;
    const int gid = blockIdx.x * GPB + (tid >> 3);   // global 8-lane group id
    const int lig = tid & 7;                         // lane in group

    // hoisted per-row invariants + register-resident state (all 50 steps)
    int   rows[MAXK], rs[MAXK], re[MAXK];
    bool  val[MAXK];
    float bi[MAXK], al[MAXK];
    float v[MAXK][4];                                // redundant per lane (no shuffles)
    #pragma unroll
    for (int k = 0; k < MAXK; k++) {
        int r = gid + k * NGROUPS;
        bool ok = r < NN;
        val[k] = ok;
        rows[k] = ok ? r : 0;
        rs[k] = ok ? __ldg(&g_row_start[r]) : 0;
        re[k] = ok ? __ldg(&g_row_start[r + 1]) : 0;
        float b = ok ? __ldg(&bias[r]) : 0.0f;
        bi[k] = b;
        al[k] = ok ? __ldg(&g_alpha[r]) : 0.0f;
        #pragma unroll
        for (int b4 = 0; b4 < 4; b4++) v[k][b4] = b;   // v0 = bias
    }

    // prologue: scatter w * relu(v0) into acc[0]
    #pragma unroll
    for (int k = 0; k < MAXK; k++) {
        float rn = fmaxf(bi[k], 0.0f);
        for (int i = rs[k] + lig; i < re[k]; i += 8) {
            float2 p = __ldcs(&g_csc[i]);
            float m = rn * p.x;
            red_v4(&g_acc[0][4 * __float_as_int(p.y)], m, m, m, m);
        }
    }

    int ep = 0;
    // barrier helper inlined each use
    {
        __threadfence();
        __syncthreads();
        if (tid == 0) {
            atomicAdd(&g_bar, 1);
            ep = 1;
            volatile int* pb = &g_bar;
            while (*pb < ep * PBLK) { }
        }
        __syncthreads();
    }
    ep = 1;

    for (int t = 0; t < NT; t++) {
        const int cur = t & 1, nxt = cur ^ 1;
        float* __restrict__ acc_c = g_acc[cur];
        float* __restrict__ acc_n = g_acc[nxt];

        #pragma unroll
        for (int k = 0; k < MAXK; k++) {
            if (!val[k]) continue;
            const int row = rows[k];
            float4 a = *reinterpret_cast<const float4*>(acc_c + 4 * row);
            float sums[4] = {a.x, a.y, a.z, a.w};
            float rn[4];
            #pragma unroll
            for (int b = 0; b < 4; b++) {
                float xv = __ldcs(&x[(b * NT + t) * NN + row]);
                float vo = v[k][b];
                float vn = fmaf(al[k], bi[k] - vo + sums[b] + xv, vo);
                v[k][b] = vn;
                rn[b] = fmaxf(vn, 0.0f);
            }
            if (lig == 0)   // clear own slot for reuse at t+2
                *reinterpret_cast<float4*>(acc_c + 4 * row) =
                    make_float4(0.f, 0.f, 0.f, 0.f);
            if (lig < 4)
                __stcs(&out[(lig * NT + t) * NN + row], rn[lig]);

            if (t != NT - 1) {
                for (int i = rs[k] + lig; i < re[k]; i += 8) {
                    float2 p = __ldcs(&g_csc[i]);
                    red_v4(&acc_n[4 * __float_as_int(p.y)],
                           rn[0] * p.x, rn[1] * p.x, rn[2] * p.x, rn[3] * p.x);
                }
            }
        }

        if (t != NT - 1) {
            __threadfence();
            __syncthreads();
            if (tid == 0) {
                atomicAdd(&g_bar, 1);
                const int target = (ep + 1) * PBLK;
                volatile int* pb = &g_bar;
                while (*pb < target) { }
            }
            __syncthreads();
            ep++;
        }
    }
}

// ---------------- launch ----------------
extern "C" void kernel_launch(void* const* d_in, const int* in_sizes, int n_in,
                              void* d_out, int out_size) {
    const float* x      = (const float*)d_in[0];  // [B,T,N]
    const float* bias   = (const float*)d_in[1];  // [N]
    const float* tcst   = (const float*)d_in[2];  // [N]
    const float* sign   = (const float*)d_in[3];  // [E]
    const float* cnt    = (const float*)d_in[4];  // [E]
    const float* strg   = (const float*)d_in[5];  // [E]
    const int*   srcidx = (const int*)d_in[6];    // [E]
    const int*   tgtidx = (const int*)d_in[7];    // [E]
    float* out = (float*)d_out;                   // [B,T,N]

    const int nblk = (NN + 255) / 256;
    const int eblk = (NE + 255) / 256;

    init_kernel<<<nblk, 256>>>(tcst);
    hist_kernel<<<eblk, 256>>>(srcidx);
    scan_kernel<<<1, 1024>>>();
    scatter_kernel<<<eblk, 256>>>(srcidx, tgtidx, sign, cnt, strg);

    net_kernel<<<PBLK, THREADS>>>(bias, x, out);

    (void)in_sizes; (void)n_in; (void)out_size;
}

// round 5
// speedup vs baseline: 1.2450x; 1.2450x over previous
#include <cuda_runtime.h>
#include <cuda_bf16.h>
#include <cstdint>

// Problem constants (fixed by the dataset)
#define NN 50000
#define NE 1600000
#define NT 50
#define FDT 0.02f

// Persistent-kernel geometry: 296 = 148 SMs * 2 blocks, guaranteed co-resident
#define PBLK 296
#define THREADS 512
#define GPB (THREADS / 8)           // 64 groups of 8 lanes per block
#define NGROUPS (PBLK * GPB)        // 18944
#define MAXK 3                      // ceil(NN / NGROUPS)
#define CHUNK 169                   // ceil(NN / PBLK) for the grid scan
#define NBAR 64

// ---------------- device scratch (static, no allocations) ----------------
__device__ float2 g_csr[NE];            // per edge: {weight, bitcast(src)} sorted by TARGET
__device__ int    g_row_start[NN + 1];  // CSR row offsets (by target)
__device__ int    g_deg[NN];
__device__ int    g_cursor[NN];
__device__ float  g_r[2][NN * 4];       // relu(v) rates, ping-pong, layout [node][batch]
__device__ float  g_alpha[NN];          // dt / max(tau, dt)
__device__ int    g_bars[NBAR];         // per-barrier arrival counters (reset by init)
__device__ int    g_part[PBLK];         // scan partials

// ---------------- init kernel (normal launch; resets barrier state each replay) ----
__global__ void init_kernel(const float* __restrict__ bias,
                            const float* __restrict__ tc) {
    int i = blockIdx.x * blockDim.x + threadIdx.x;
    if (i < NBAR) g_bars[i] = 0;
    if (i < NN) {
        g_deg[i] = 0;
        g_cursor[i] = 0;
        g_alpha[i] = FDT / fmaxf(tc[i], FDT);
        float rb = fmaxf(bias[i], 0.0f);
        *reinterpret_cast<float4*>(&g_r[0][4 * i]) = make_float4(rb, rb, rb, rb);
    }
}

// ---------------- grid barrier (indexed, monotonic per-counter) ----------------
__device__ __forceinline__ void grid_barrier(int idx) {
    __threadfence();                       // publish stores + CCTL.IVALL (L1 inval)
    __syncthreads();
    if (threadIdx.x == 0) {
        atomicAdd(&g_bars[idx], 1);
        volatile int* p = &g_bars[idx];
        while (*p < PBLK) { }
    }
    __syncthreads();
}

// ---------------- the whole problem in one persistent kernel ----------------
__global__ void __launch_bounds__(THREADS, 2)
net_kernel(const float* __restrict__ bias,
           const float* __restrict__ x,
           float* __restrict__ out,
           const int* __restrict__ src, const int* __restrict__ tgt,
           const float* __restrict__ sign, const float* __restrict__ cnt,
           const float* __restrict__ strg) {
    const int tid = threadIdx.x;
    const int bid = blockIdx.x;

    // ---------- phase 1: degree histogram (by target) ----------
    for (int i = bid * THREADS + tid; i < NE; i += PBLK * THREADS)
        atomicAdd(&g_deg[tgt[i]], 1);
    grid_barrier(0);

    // ---------- phase 2: grid-wide exclusive scan of g_deg ----------
    {
        __shared__ int s_scan[512];
        __shared__ int s_off;
        const int cbase = bid * CHUNK;
        const int n = (cbase + CHUNK <= NN) ? CHUNK : (NN - cbase);  // n >= 1 for all blocks
        int dval = (tid < n) ? g_deg[cbase + tid] : 0;
        s_scan[tid] = dval;
        __syncthreads();
        // Hillis-Steele inclusive scan over 512 slots
        #pragma unroll
        for (int o = 1; o < 512; o <<= 1) {
            int v = (tid >= o) ? s_scan[tid - o] : 0;
            __syncthreads();
            s_scan[tid] += v;
            __syncthreads();
        }
        if (tid == 0) g_part[bid] = s_scan[511];
        grid_barrier(1);
        // block offset = sum of partials of lower blocks
        {
            __shared__ int s_red[16];
            int acc = 0;
            for (int j = tid; j < bid; j += THREADS) acc += g_part[j];
            #pragma unroll
            for (int o = 16; o; o >>= 1) acc += __shfl_xor_sync(0xffffffffu, acc, o);
            if ((tid & 31) == 0) s_red[tid >> 5] = acc;
            __syncthreads();
            if (tid == 0) {
                int s = 0;
                #pragma unroll
                for (int w = 0; w < 16; w++) s += s_red[w];
                s_off = s;
            }
            __syncthreads();
        }
        if (tid < n) g_row_start[cbase + tid] = s_off + s_scan[tid] - dval;  // exclusive
        if (bid == PBLK - 1 && tid == 0) g_row_start[NN] = s_off + s_scan[511];
    }
    grid_barrier(2);

    // ---------- phase 3: scatter edges into target-sorted CSR ----------
    for (int i = bid * THREADS + tid; i < NE; i += PBLK * THREADS) {
        float w = sign[i] * fmaxf(cnt[i], 0.0f) * fmaxf(strg[i], 0.0f);
        int t_ = tgt[i];
        int pos = atomicAdd(&g_cursor[t_], 1);
        g_csr[g_row_start[t_] + pos] = make_float2(w, __int_as_float(src[i]));
    }
    grid_barrier(3);

    // ---------- phase 4: 50 recurrent steps (R3 engine) ----------
    const int gid = bid * GPB + (tid >> 3);          // global 8-lane group id
    const int lig = tid & 7;                         // lane in group (batch id if < 4)
    const unsigned gmask = 0xFFu << (((tid & 31) >> 3) * 8);

    // hoisted per-row invariants (registers for all 50 steps)
    int   rows[MAXK], rs[MAXK], re[MAXK];
    bool  val[MAXK];
    float vb[MAXK], bi[MAXK], al[MAXK];
    #pragma unroll
    for (int k = 0; k < MAXK; k++) {
        int r = gid + k * NGROUPS;
        bool ok = r < NN;
        val[k] = ok;
        rows[k] = ok ? r : 0;
        rs[k] = ok ? g_row_start[r] : 0;
        re[k] = ok ? g_row_start[r + 1] : 0;
        float b = ok ? __ldg(&bias[r]) : 0.0f;
        bi[k] = b;
        vb[k] = b;                                   // v starts at bias
        al[k] = ok ? g_alpha[rows[k]] : 0.0f;
    }

    for (int t = 0; t < NT; t++) {
        const float* __restrict__ rates = g_r[t & 1];
        float* __restrict__       rnew  = g_r[(t & 1) ^ 1];

        // prefetch stimulus for this step (batch = lig for lanes 0..3)
        float xs[MAXK];
        #pragma unroll
        for (int k = 0; k < MAXK; k++)
            xs[k] = (val[k] && lig < 4) ? __ldcs(&x[(lig * NT + t) * NN + rows[k]]) : 0.0f;

        #pragma unroll
        for (int k = 0; k < MAXK; k++) {
            float ax = 0.f, ay = 0.f, az = 0.f, aw = 0.f;
            for (int i = rs[k] + lig; i < re[k]; i += 8) {
                float2 p = __ldcs(&g_csr[i]);
                const float4 r4 =
                    *reinterpret_cast<const float4*>(rates + 4 * __float_as_int(p.y));
                ax = fmaf(r4.x, p.x, ax);
                ay = fmaf(r4.y, p.x, ay);
                az = fmaf(r4.z, p.x, az);
                aw = fmaf(r4.w, p.x, aw);
            }
            // reduce within the 8-lane group
            #pragma unroll
            for (int o = 4; o; o >>= 1) {
                ax += __shfl_xor_sync(gmask, ax, o, 8);
                ay += __shfl_xor_sync(gmask, ay, o, 8);
                az += __shfl_xor_sync(gmask, az, o, 8);
                aw += __shfl_xor_sync(gmask, aw, o, 8);
            }
            if (val[k] && lig < 4) {
                float sum = (lig == 0) ? ax : (lig == 1) ? ay : (lig == 2) ? az : aw;
                float vo = vb[k];
                float vn = fmaf(al[k], bi[k] - vo + sum + xs[k], vo);
                vb[k] = vn;
                float rn = fmaxf(vn, 0.f);
                rnew[4 * rows[k] + lig] = rn;
                __stcs(&out[(lig * NT + t) * NN + rows[k]], rn);
            }
        }

        if (t != NT - 1) grid_barrier(4 + t);
    }
}

// ---------------- launch ----------------
extern "C" void kernel_launch(void* const* d_in, const int* in_sizes, int n_in,
                              void* d_out, int out_size) {
    const float* x      = (const float*)d_in[0];  // [B,T,N]
    const float* bias   = (const float*)d_in[1];  // [N]
    const float* tcst   = (const float*)d_in[2];  // [N]
    const float* sign   = (const float*)d_in[3];  // [E]
    const float* cnt    = (const float*)d_in[4];  // [E]
    const float* strg   = (const float*)d_in[5];  // [E]
    const int*   srcidx = (const int*)d_in[6];    // [E]
    const int*   tgtidx = (const int*)d_in[7];    // [E]
    float* out = (float*)d_out;                   // [B,T,N]

    const int nblk = (NN + 255) / 256;
    init_kernel<<<nblk, 256>>>(bias, tcst);
    net_kernel<<<PBLK, THREADS>>>(bias, x, out, srcidx, tgtidx, sign, cnt, strg);

    (void)in_sizes; (void)n_in; (void)out_size;
}

// round 7
// speedup vs baseline: 1.2624x; 1.0140x over previous
#include <cuda_runtime.h>
#include <cuda_bf16.h>
#include <cstdint>

// Problem constants (fixed by the dataset)
#define NN 50000
#define NE 1600000
#define NT 50
#define FDT 0.02f

// Persistent-kernel geometry: 444 = 148 SMs * 3 blocks, co-resident at <=40 regs
#define PBLK 444
#define THREADS 512
#define GPB (THREADS / 4)           // 128 groups of 4 lanes per block
#define NGROUPS (PBLK * GPB)        // 56832 >= NN -> exactly one row per group
#define CHUNK 113                   // ceil(NN / PBLK) for the grid scan
#define NBAR 64

// ---------------- device scratch (static, no allocations) ----------------
__device__ float2 g_csr[NE];            // per edge: {weight, bitcast(src)} sorted by TARGET
__device__ int    g_row_start[NN + 1];
__device__ int    g_deg[NN];
__device__ int    g_cursor[NN];
__device__ float  g_r[2][NN * 4];       // relu(v) rates, ping-pong, [node][batch]
__device__ float  g_alpha[NN];
__device__ int    g_bars[NBAR];         // per-barrier arrival counters (reset by init)
__device__ int    g_part[PBLK];         // scan partials

// ---------------- init kernel (resets barrier state each graph replay) ----------
__global__ void init_kernel(const float* __restrict__ bias,
                            const float* __restrict__ tc) {
    int i = blockIdx.x * blockDim.x + threadIdx.x;
    if (i < NBAR) g_bars[i] = 0;
    if (i < NN) {
        g_deg[i] = 0;
        g_cursor[i] = 0;
        g_alpha[i] = FDT / fmaxf(tc[i], FDT);
        float rb = fmaxf(bias[i], 0.0f);
        *reinterpret_cast<float4*>(&g_r[0][4 * i]) = make_float4(rb, rb, rb, rb);
    }
}

// ---------------- barriers ----------------
// Full barrier (prep phases): fences + L1 invalidate on both sides.
__device__ __forceinline__ void full_barrier(int idx) {
    __threadfence();
    __syncthreads();
    if (threadIdx.x == 0) {
        atomicAdd(&g_bars[idx], 1);
        volatile int* p = &g_bars[idx];
        while (*p < PBLK) { __nanosleep(64); }
    }
    __syncthreads();
    __threadfence();                    // acquire-side invalidate
}

// Light barrier (step loop): scoped release/acquire atomics, NO CCTL.IVALL,
// so the L1-resident CSR survives. All cross-step mutable data moves via
// ld.cg/st.cg (L2-only), so skipping the L1 invalidate is safe. This is the
// cooperative-groups grid.sync() pattern (morally strong via bar.sync chain).
__device__ __forceinline__ void light_barrier(int idx) {
    __syncthreads();
    if (threadIdx.x == 0) {
        int* a = &g_bars[idx];
        asm volatile("red.release.gpu.add.u32 [%0], 1;" :: "l"(a) : "memory");
        unsigned v;
        do {
            asm volatile("ld.relaxed.gpu.u32 %0, [%1];" : "=r"(v) : "l"(a));
            if (v < PBLK) __nanosleep(32);
        } while (v < PBLK);
        unsigned d;
        asm volatile("atom.acquire.gpu.add.u32 %0, [%1], 0;"
                     : "=r"(d) : "l"(a) : "memory");
    }
    __syncthreads();
}

// ---------------- the whole problem in one persistent kernel ----------------
__global__ void __launch_bounds__(THREADS, 3)
net_kernel(const float* __restrict__ bias,
           const float* __restrict__ x,
           float* __restrict__ out,
           const int* __restrict__ src, const int* __restrict__ tgt,
           const float* __restrict__ sign, const float* __restrict__ cnt,
           const float* __restrict__ strg) {
    const int tid = threadIdx.x;
    const int bid = blockIdx.x;

    // ---------- phase 1: degree histogram (by target) ----------
    for (int i = bid * THREADS + tid; i < NE; i += PBLK * THREADS)
        atomicAdd(&g_deg[tgt[i]], 1);
    full_barrier(0);

    // ---------- phase 2: grid-wide exclusive scan of g_deg ----------
    {
        __shared__ int s_scan[THREADS];
        __shared__ int s_off;
        const int cbase = bid * CHUNK;
        int n = NN - cbase;
        if (n > CHUNK) n = CHUNK;
        if (n < 0) n = 0;
        int dval = (tid < n) ? g_deg[cbase + tid] : 0;
        s_scan[tid] = dval;
        __syncthreads();
        #pragma unroll
        for (int o = 1; o < THREADS; o <<= 1) {
            int v = (tid >= o) ? s_scan[tid - o] : 0;
            __syncthreads();
            s_scan[tid] += v;
            __syncthreads();
        }
        if (tid == 0) g_part[bid] = s_scan[THREADS - 1];
        full_barrier(1);
        {
            __shared__ int s_red[16];
            int acc = 0;
            for (int j = tid; j < bid; j += THREADS) acc += g_part[j];
            #pragma unroll
            for (int o = 16; o; o >>= 1) acc += __shfl_xor_sync(0xffffffffu, acc, o);
            if ((tid & 31) == 0) s_red[tid >> 5] = acc;
            __syncthreads();
            if (tid == 0) {
                int s = 0;
                #pragma unroll
                for (int w = 0; w < 16; w++) s += s_red[w];
                s_off = s;
            }
            __syncthreads();
        }
        if (tid < n) g_row_start[cbase + tid] = s_off + s_scan[tid] - dval;
        if (bid == PBLK - 1 && tid == 0) g_row_start[NN] = s_off + s_scan[THREADS - 1];
    }
    full_barrier(2);

    // ---------- phase 3: scatter edges into target-sorted CSR ----------
    for (int i = bid * THREADS + tid; i < NE; i += PBLK * THREADS) {
        float w = sign[i] * fmaxf(cnt[i], 0.0f) * fmaxf(strg[i], 0.0f);
        int t_ = tgt[i];
        int pos = atomicAdd(&g_cursor[t_], 1);
        g_csr[g_row_start[t_] + pos] = make_float2(w, __int_as_float(src[i]));
    }
    full_barrier(3);

    // ---------- phase 4: 50 recurrent steps ----------
    const int gid = bid * GPB + (tid >> 2);          // one row per 4-lane group
    const int lig = tid & 3;                         // lane in group == batch id
    const unsigned lbase = (unsigned)(tid & 31) & ~3u;
    const unsigned gmask = 0xFu << lbase;

    const bool ok = gid < NN;
    const int row = ok ? gid : 0;
    const int rs = ok ? g_row_start[row] : 0;
    const int re = ok ? g_row_start[row + 1] : 0;
    const float bi = ok ? __ldg(&bias[row]) : 0.0f;
    const float al = ok ? g_alpha[row] : 0.0f;
    float vb = bi;                                   // v starts at bias
    const float* xp = x + (size_t)lig * NT * NN + row;
    float*       op = out + (size_t)lig * NT * NN + row;

    for (int t = 0; t < NT; t++) {
        const float* __restrict__ rates = g_r[t & 1];
        float* __restrict__       rnew  = g_r[(t & 1) ^ 1];

        float xv = ok ? __ldcg(xp) : 0.0f;

        float ax = 0.f, ay = 0.f, az = 0.f, aw = 0.f;
        int i = rs + lig;
        for (; i + 4 < re; i += 8) {                 // 2 edges per lane per iter
            float2 p0 = g_csr[i];                    // L1-resident across steps
            float2 p1 = g_csr[i + 4];
            float4 r0 = __ldcg(reinterpret_cast<const float4*>(
                                   rates + 4 * __float_as_int(p0.y)));
            float4 r1 = __ldcg(reinterpret_cast<const float4*>(
                                   rates + 4 * __float_as_int(p1.y)));
            ax = fmaf(r0.x, p0.x, ax);
            ay = fmaf(r0.y, p0.x, ay);
            az = fmaf(r0.z, p0.x, az);
            aw = fmaf(r0.w, p0.x, aw);
            ax = fmaf(r1.x, p1.x, ax);
            ay = fmaf(r1.y, p1.x, ay);
            az = fmaf(r1.z, p1.x, az);
            aw = fmaf(r1.w, p1.x, aw);
        }
        if (i < re) {
            float2 p0 = g_csr[i];
            float4 r0 = __ldcg(reinterpret_cast<const float4*>(
                                   rates + 4 * __float_as_int(p0.y)));
            ax = fmaf(r0.x, p0.x, ax);
            ay = fmaf(r0.y, p0.x, ay);
            az = fmaf(r0.z, p0.x, az);
            aw = fmaf(r0.w, p0.x, aw);
        }
        // reduce within the 4-lane group
        #pragma unroll
        for (int o = 2; o; o >>= 1) {
            ax += __shfl_xor_sync(gmask, ax, o, 4);
            ay += __shfl_xor_sync(gmask, ay, o, 4);
            az += __shfl_xor_sync(gmask, az, o, 4);
            aw += __shfl_xor_sync(gmask, aw, o, 4);
        }
        if (ok) {
            float sum = (lig == 0) ? ax : (lig == 1) ? ay : (lig == 2) ? az : aw;
            float vn = fmaf(al, bi - vb + sum + xv, vb);
            vb = vn;
            float rn = fmaxf(vn, 0.f);
            __stcg(&rnew[4 * row + lig], rn);        // L2-only: no stale L1 copies
            __stcs(op, rn);
        }
        xp += NN;
        op += NN;

        if (t != NT - 1) light_barrier(4 + t);
    }
}

// ---------------- launch ----------------
extern "C" void kernel_launch(void* const* d_in, const int* in_sizes, int n_in,
                              void* d_out, int out_size) {
    const float* x      = (const float*)d_in[0];  // [B,T,N]
    const float* bias   = (const float*)d_in[1];  // [N]
    const float* tcst   = (const float*)d_in[2];  // [N]
    const float* sign   = (const float*)d_in[3];  // [E]
    const float* cnt    = (const float*)d_in[4];  // [E]
    const float* strg   = (const float*)d_in[5];  // [E]
    const int*   srcidx = (const int*)d_in[6];    // [E]
    const int*   tgtidx = (const int*)d_in[7];    // [E]
    float* out = (float*)d_out;                   // [B,T,N]

    const int nblk = (NN + 255) / 256;
    init_kernel<<<nblk, 256>>>(bias, tcst);
    net_kernel<<<PBLK, THREADS>>>(bias, x, out, srcidx, tgtidx, sign, cnt, strg);

    (void)in_sizes; (void)n_in; (void)out_size;
}